// round 6
// baseline (speedup 1.0000x reference)
#include <cuda_runtime.h>
#include <math.h>

#define NN 100000
#define NE 1600000
#define SCAN_B 512
#define NBLK ((NN + SCAN_B - 1) / SCAN_B)   // 196

// ---------------- scratch (static device globals; no allocation) ----------------
__device__ int   g_is64;
__device__ int   g_hist[NN];
__device__ int   g_rowptr[NN + 1];
__device__ int   g_cursor[NN];
__device__ int   g_bsum[NBLK];
__device__ int   g_srcsorted[NE];
__device__ __align__(16) float g_mean[(size_t)NN * 128];
__device__ __align__(16) float g_h[(size_t)NN * 128];
__device__ __align__(16) float g_B1[256 * 128];   // [W1l ; W1r] transposed -> [k][j]
__device__ __align__(16) float g_B2[256 * 64];    // [W2l ; W2r] transposed -> [k][j]

// ---------------- edge dtype detection: int64 vs int32 ----------------
__global__ void detect_kernel(const void* __restrict__ ei) {
    if (threadIdx.x == 0 && blockIdx.x == 0) {
        const long long* p64 = (const long long*)ei;
        int ok = 1;
        for (int i = 0; i < 256; i++) {
            long long v = p64[i];
            if (v < 0 || v >= NN) { ok = 0; break; }
        }
        g_is64 = ok;
    }
}

__device__ __forceinline__ int load_edge(const void* ei, int idx, int is64) {
    if (is64) {
        long long v = ((const long long*)ei)[idx];
        return (int)v;
    } else {
        return ((const int*)ei)[idx];
    }
}

// ---------------- CSR build ----------------
__global__ void zero_hist_kernel() {
    int i = blockIdx.x * blockDim.x + threadIdx.x;
    if (i < NN) g_hist[i] = 0;
}

__global__ void hist_kernel(const void* __restrict__ ei) {
    const int is64 = g_is64;
    for (int e = blockIdx.x * blockDim.x + threadIdx.x; e < NE;
         e += gridDim.x * blockDim.x) {
        int dst = load_edge(ei, NE + e, is64);
        if (dst >= 0 && dst < NN) atomicAdd(&g_hist[dst], 1);
    }
}

__global__ void scan_block_kernel() {
    __shared__ int sh[SCAN_B];
    int i = blockIdx.x * SCAN_B + threadIdx.x;
    int v = (i < NN) ? g_hist[i] : 0;
    sh[threadIdx.x] = v;
    __syncthreads();
    #pragma unroll
    for (int off = 1; off < SCAN_B; off <<= 1) {
        int t = (threadIdx.x >= off) ? sh[threadIdx.x - off] : 0;
        __syncthreads();
        sh[threadIdx.x] += t;
        __syncthreads();
    }
    if (i < NN) g_rowptr[i] = sh[threadIdx.x] - v;   // exclusive within block
    if (threadIdx.x == SCAN_B - 1) g_bsum[blockIdx.x] = sh[SCAN_B - 1];
}

__global__ void scan_bsum_kernel() {
    if (threadIdx.x == 0 && blockIdx.x == 0) {
        int acc = 0;
        for (int i = 0; i < NBLK; i++) { int v = g_bsum[i]; g_bsum[i] = acc; acc += v; }
    }
}

__global__ void add_offsets_kernel() {
    int i = blockIdx.x * SCAN_B + threadIdx.x;
    if (i < NN) {
        int r = g_rowptr[i] + g_bsum[blockIdx.x];
        g_rowptr[i] = r;
        g_cursor[i] = r;
    }
    if (i == 0) g_rowptr[NN] = g_rowptr[NN];   // placeholder; fixed below
}

__global__ void finalize_rowptr_kernel() {
    if (threadIdx.x == 0 && blockIdx.x == 0) {
        // total edges kept = sum of hist = last cursor start + its count; recompute safely:
        // rowptr[NN] = rowptr[NN-1] + hist[NN-1]
        g_rowptr[NN] = g_rowptr[NN - 1] + g_hist[NN - 1];
    }
}

__global__ void scatter_kernel(const void* __restrict__ ei) {
    const int is64 = g_is64;
    for (int e = blockIdx.x * blockDim.x + threadIdx.x; e < NE;
         e += gridDim.x * blockDim.x) {
        int src = load_edge(ei, e, is64);
        int dst = load_edge(ei, NE + e, is64);
        if (dst >= 0 && dst < NN) {
            if (src < 0) src = 0;
            if (src >= NN) src = NN - 1;
            int pos = atomicAdd(&g_cursor[dst], 1);
            g_srcsorted[pos] = src;
        }
    }
}

// ---------------- weight transpose: B[k][j] = [Wl;Wr][j][k] ----------------
__global__ void build_B1_kernel(const float* __restrict__ W1l, const float* __restrict__ W1r) {
    int idx = blockIdx.x * blockDim.x + threadIdx.x;   // 256*128 entries
    if (idx >= 256 * 128) return;
    int k = idx >> 7, j = idx & 127;
    g_B1[idx] = (k < 128) ? W1l[j * 128 + k] : W1r[j * 128 + (k - 128)];
}

__global__ void build_B2_kernel(const float* __restrict__ W2l, const float* __restrict__ W2r) {
    int idx = blockIdx.x * blockDim.x + threadIdx.x;   // 256*64 entries
    if (idx >= 256 * 64) return;
    int k = idx >> 6, j = idx & 63;
    g_B2[idx] = (k < 128) ? W2l[j * 128 + k] : W2r[j * 128 + (k - 128)];
}

// ---------------- mean aggregation: warp per node, gather via CSR ----------------
template <bool USE_GH>
__global__ void agg_mean_kernel(const float* __restrict__ featparam) {
    int node = blockIdx.x * 8 + threadIdx.y;
    if (node >= NN) return;
    const float* feat = USE_GH ? (const float*)g_h : featparam;
    int lane = threadIdx.x;
    int s = g_rowptr[node], e = g_rowptr[node + 1];
    const float4* f4 = (const float4*)feat;
    float4 acc = make_float4(0.f, 0.f, 0.f, 0.f);
    int i = s;
    for (; i + 4 <= e; i += 4) {                 // 4-way MLP
        int s0 = g_srcsorted[i + 0], s1 = g_srcsorted[i + 1];
        int s2 = g_srcsorted[i + 2], s3 = g_srcsorted[i + 3];
        float4 v0 = f4[(size_t)s0 * 32 + lane];
        float4 v1 = f4[(size_t)s1 * 32 + lane];
        float4 v2 = f4[(size_t)s2 * 32 + lane];
        float4 v3 = f4[(size_t)s3 * 32 + lane];
        acc.x += v0.x + v1.x + v2.x + v3.x;
        acc.y += v0.y + v1.y + v2.y + v3.y;
        acc.z += v0.z + v1.z + v2.z + v3.z;
        acc.w += v0.w + v1.w + v2.w + v3.w;
    }
    for (; i < e; i++) {
        int s0 = g_srcsorted[i];
        float4 v = f4[(size_t)s0 * 32 + lane];
        acc.x += v.x; acc.y += v.y; acc.z += v.z; acc.w += v.w;
    }
    float inv = (e > s) ? 1.0f / (float)(e - s) : 0.0f;
    acc.x *= inv; acc.y *= inv; acc.z *= inv; acc.w *= inv;
    ((float4*)g_mean)[(size_t)node * 32 + lane] = acc;
}

// ---------------- fused GEMM: out = [g_mean | self] @ B + bias (+relu) ----------------
template <int BN, int TN, bool RELU, bool SELF_GH, bool OUT_GH, bool USE_B1>
__global__ void __launch_bounds__(256)
gemm_kernel(const float* __restrict__ AselfParam, const float* __restrict__ bias,
            float* __restrict__ outParam) {
    __shared__ float As[16][128];
    __shared__ float Bs[16][BN];
    const float* Aself = SELF_GH ? (const float*)g_h : AselfParam;
    const float* B     = USE_B1 ? (const float*)g_B1 : (const float*)g_B2;
    float*       out   = OUT_GH ? (float*)g_h : outParam;

    const int tid = threadIdx.x;
    const int node0 = blockIdx.x * 128;
    const int my = tid >> 4;      // 0..15 -> node group of 8
    const int tx = tid & 15;      // 0..15 -> col group of TN

    float acc[8][TN];
    #pragma unroll
    for (int i = 0; i < 8; i++)
        #pragma unroll
        for (int j = 0; j < TN; j++) acc[i][j] = 0.f;

    #pragma unroll 1
    for (int kt = 0; kt < 16; kt++) {             // 256 / BK
        const float* srcA = (kt < 8) ? (const float*)g_mean : Aself;
        const int k0m = (kt & 7) * 16;
        // stage A tile (transposed into [k][m])
        #pragma unroll
        for (int l = 0; l < 2; l++) {
            int li = tid * 2 + l;                 // 0..511
            int m = li >> 2;
            int kq = li & 3;
            int node = node0 + m;
            if (node >= NN) node = NN - 1;
            float4 v = *(const float4*)(srcA + (size_t)node * 128 + k0m + kq * 4);
            As[kq * 4 + 0][m] = v.x;
            As[kq * 4 + 1][m] = v.y;
            As[kq * 4 + 2][m] = v.z;
            As[kq * 4 + 3][m] = v.w;
        }
        // stage B tile (already [k][j] in gmem)
        #pragma unroll
        for (int l = 0; l < (16 * BN) / (4 * 256); l++) {
            int li = tid + l * 256;
            int k = li / (BN / 4);
            int j4 = li % (BN / 4);
            float4 v = *(const float4*)(B + (size_t)(kt * 16 + k) * BN + j4 * 4);
            *(float4*)&Bs[k][j4 * 4] = v;
        }
        __syncthreads();
        #pragma unroll
        for (int kk = 0; kk < 16; kk++) {
            float a[8], b[TN];
            *(float4*)&a[0] = *(const float4*)&As[kk][my * 8];
            *(float4*)&a[4] = *(const float4*)&As[kk][my * 8 + 4];
            *(float4*)&b[0] = *(const float4*)&Bs[kk][tx * TN];
            if (TN == 8) *(float4*)&b[4] = *(const float4*)&Bs[kk][tx * TN + 4];
            #pragma unroll
            for (int i = 0; i < 8; i++)
                #pragma unroll
                for (int j = 0; j < TN; j++)
                    acc[i][j] = fmaf(a[i], b[j], acc[i][j]);
        }
        __syncthreads();
    }

    float bi[TN];
    #pragma unroll
    for (int j = 0; j < TN; j++) bi[j] = bias[tx * TN + j];

    #pragma unroll
    for (int i = 0; i < 8; i++) {
        int node = node0 + my * 8 + i;
        if (node < NN) {
            float c[TN];
            #pragma unroll
            for (int j = 0; j < TN; j++) {
                float v = acc[i][j] + bi[j];
                c[j] = RELU ? fmaxf(v, 0.f) : v;
            }
            float* op = out + (size_t)node * BN + tx * TN;
            *(float4*)op = make_float4(c[0], c[1], c[2], c[3]);
            if (TN == 8) *(float4*)(op + 4) = make_float4(c[4], c[5], c[6], c[7]);
        }
    }
}

// ---------------- log_softmax over 64 classes, warp per node ----------------
__global__ void logsoftmax_kernel(float* __restrict__ out) {
    int node = blockIdx.x * 8 + threadIdx.y;
    if (node >= NN) return;
    int lane = threadIdx.x;
    float2* row = (float2*)(out + (size_t)node * 64);
    float2 v = row[lane];
    float m = fmaxf(v.x, v.y);
    #pragma unroll
    for (int o = 16; o; o >>= 1) m = fmaxf(m, __shfl_xor_sync(0xffffffffu, m, o));
    float s = expf(v.x - m) + expf(v.y - m);
    #pragma unroll
    for (int o = 16; o; o >>= 1) s += __shfl_xor_sync(0xffffffffu, s, o);
    float lse = m + logf(s);
    v.x -= lse; v.y -= lse;
    row[lane] = v;
}

// ---------------- launch ----------------
extern "C" void kernel_launch(void* const* d_in, const int* in_sizes, int n_in,
                              void* d_out, int out_size) {
    const float* x   = (const float*)d_in[0];
    const void*  ei  = d_in[1];                 // int32 or int64, detected on device
    const float* W1l = (const float*)d_in[2];
    const float* b1l = (const float*)d_in[3];
    const float* W1r = (const float*)d_in[4];
    const float* W2l = (const float*)d_in[5];
    const float* b2l = (const float*)d_in[6];
    const float* W2r = (const float*)d_in[7];
    float*       out = (float*)d_out;

    // edge dtype detection, then CSR build (counting sort by dst)
    detect_kernel<<<1, 32>>>(ei);
    zero_hist_kernel<<<(NN + 255) / 256, 256>>>();
    hist_kernel<<<2048, 256>>>(ei);
    scan_block_kernel<<<NBLK, SCAN_B>>>();
    scan_bsum_kernel<<<1, 32>>>();
    add_offsets_kernel<<<NBLK, SCAN_B>>>();
    finalize_rowptr_kernel<<<1, 32>>>();
    scatter_kernel<<<2048, 256>>>(ei);

    // weight transposes
    build_B1_kernel<<<(256 * 128 + 255) / 256, 256>>>(W1l, W1r);
    build_B2_kernel<<<(256 * 64 + 255) / 256, 256>>>(W2l, W2r);

    const int aggGrid  = (NN + 7) / 8;
    const int gemmGrid = (NN + 127) / 128;

    // layer 1: agg(x) -> g_mean; gemm([g_mean|x] @ B1) -> g_h (relu)
    agg_mean_kernel<false><<<aggGrid, dim3(32, 8)>>>(x);
    gemm_kernel<128, 8, true, false, true, true><<<gemmGrid, 256>>>(x, b1l, nullptr);

    // layer 2: agg(g_h) -> g_mean; gemm([g_mean|g_h] @ B2) -> out
    agg_mean_kernel<true><<<aggGrid, dim3(32, 8)>>>(nullptr);
    gemm_kernel<64, 4, false, true, false, false><<<gemmGrid, 256>>>(nullptr, b2l, out);

    // log_softmax in place on d_out
    logsoftmax_kernel<<<aggGrid, dim3(32, 8)>>>(out);
}